// round 4
// baseline (speedup 1.0000x reference)
#include <cuda_runtime.h>
#include <cstdint>
#include <math.h>

#define N_ELEM 256
#define T_SEQ  32
#define H_DIM  512
#define MAXS   (N_ELEM * T_SEQ)          // worst-case executed rounds
#define NCTA_G 64                        // CTAs per layer group

// Broadcast buffers for hidden vectors (one slot per executed round, per layer)
__device__ float    g_h0[(size_t)MAXS * H_DIM];
__device__ float    g_h1[(size_t)MAXS * H_DIM];
// Per-CTA publish flags: flag[s][cta] = 1 once CTA cta's 8 channels of round s are visible
__device__ unsigned g_flag0[(size_t)MAXS * NCTA_G];
__device__ unsigned g_flag1[(size_t)MAXS * NCTA_G];
__device__ unsigned g_abort;             // watchdog abort flag

__device__ __forceinline__ float4 ldrx4(const float* p) {
    float4 v;
    asm volatile("ld.relaxed.gpu.global.v4.f32 {%0,%1,%2,%3}, [%4];"
                 : "=f"(v.x), "=f"(v.y), "=f"(v.z), "=f"(v.w)
                 : "l"(p) : "memory");
    return v;
}
__device__ __forceinline__ void strx1(float* p, float v) {
    asm volatile("st.relaxed.gpu.global.f32 [%0], %1;" :: "l"(p), "f"(v) : "memory");
}
__device__ __forceinline__ unsigned ld_acq(const unsigned* p) {
    unsigned v;
    asm volatile("ld.acquire.gpu.global.u32 %0, [%1];" : "=r"(v) : "l"(p) : "memory");
    return v;
}
__device__ __forceinline__ void st_rel(unsigned* p, unsigned v) {
    asm volatile("st.release.gpu.global.u32 [%0], %1;" :: "l"(p), "r"(v) : "memory");
}
// Warp-collective: wait until all 64 per-CTA flags of a round are set.
// Each lane acquires 2 flags (64 total); flags are 0 or 1.
__device__ __forceinline__ void wait_flags(const unsigned* f, int lane) {
    unsigned it = 0;
    const unsigned* p = f + lane * 2;
    for (;;) {
        unsigned a = ld_acq(p);
        unsigned b = ld_acq(p + 1);
        if (__all_sync(0xffffffffu, (int)(a & b))) return;
        if ((++it & 255u) == 0u) {
            if (ld_acq(&g_abort) != 0u) return;
            if (it >= (1u << 22)) { st_rel(&g_abort, 1u); return; }
        }
    }
}
__device__ __forceinline__ float wsum(float v) {
    v += __shfl_xor_sync(0xffffffffu, v, 16);
    v += __shfl_xor_sync(0xffffffffu, v, 8);
    v += __shfl_xor_sync(0xffffffffu, v, 4);
    v += __shfl_xor_sync(0xffffffffu, v, 2);
    v += __shfl_xor_sync(0xffffffffu, v, 1);
    return v;
}
__device__ __forceinline__ float dot4(float4 a, float4 b) {
    return a.x * b.x + a.y * b.y + a.z * b.z + a.w * b.w;
}
__device__ __forceinline__ float sigmoidf_(float v) {
    return 1.0f / (1.0f + expf(-v));
}

// Zero flags + abort; optionally write dates (as float) to out.
__global__ void init_kernel(const int* __restrict__ dates, float* __restrict__ out,
                            int write_dates) {
    size_t idx = (size_t)blockIdx.x * blockDim.x + threadIdx.x;
    size_t n4 = (size_t)MAXS * NCTA_G / 4;       // uint4 elements per flag array
    if (idx < n4) {
        reinterpret_cast<uint4*>(g_flag0)[idx] = make_uint4(0u, 0u, 0u, 0u);
        reinterpret_cast<uint4*>(g_flag1)[idx] = make_uint4(0u, 0u, 0u, 0u);
    }
    if (idx == 0) g_abort = 0u;
    if (write_dates && idx < N_ELEM) out[idx] = (float)dates[idx];
}

// Persistent 2-layer pipelined GRU.
// CTAs 0..63   = group A (layer 0): x-projection + recurrence, emits h0[s].
// CTAs 64..127 = group B (layer 1): consumes h0[s], own recurrence, emits h1[s] + states.
__global__ void __launch_bounds__(256, 1)
gru_persistent(const int* __restrict__ dates, const float* __restrict__ x,
               const float* __restrict__ Wih0, const float* __restrict__ Whh0,
               const float* __restrict__ bih0, const float* __restrict__ bhh0,
               const float* __restrict__ Wih1, const float* __restrict__ Whh1,
               const float* __restrict__ bih1, const float* __restrict__ bhh1,
               float* __restrict__ out_states) {
    __shared__ int sdates[N_ELEM];
    int tid = threadIdx.x;
    if (tid < N_ELEM) sdates[tid] = dates[tid];
    __syncthreads();

    int warp = tid >> 5, lane = tid & 31;
    bool isB = (blockIdx.x >= NCTA_G);
    int cta  = isB ? (blockIdx.x - NCTA_G) : blockIdx.x;
    int c    = cta * 8 + warp;                    // owned output channel, 0..511

    const float* Wi = isB ? Wih1 : Wih0;
    const float* Wh = isB ? Whh1 : Whh0;
    const float* bi = isB ? bih1 : bih0;
    const float* bh = isB ? bhh1 : bhh0;

    // Register-resident weights: 3 gate rows (r,z,n) x 16 k-values for both matmuls.
    float4 wi[3][4], wh[3][4];
#pragma unroll
    for (int g = 0; g < 3; g++) {
        const float4* pi = reinterpret_cast<const float4*>(
            Wi + (size_t)(g * H_DIM + c) * H_DIM + lane * 16);
        const float4* ph = reinterpret_cast<const float4*>(
            Wh + (size_t)(g * H_DIM + c) * H_DIM + lane * 16);
#pragma unroll
        for (int j = 0; j < 4; j++) { wi[g][j] = pi[j]; wh[g][j] = ph[j]; }
    }
    float b_r  = bi[c] + bh[c];
    float b_z  = bi[H_DIM + c] + bh[H_DIM + c];
    float b_in = bi[2 * H_DIM + c];
    float b_hn = bh[2 * H_DIM + c];
    float hcur = 0.0f;

    float*    myH    = isB ? g_h1    : g_h0;
    unsigned* myFlag = isB ? g_flag1 : g_flag0;

    int s = 0;                                    // global executed-round index
    for (int n = 0; n < N_ELEM; n++) {
        bool run = (n == 0) || (sdates[n] != sdates[n - 1]);
        if (!run) {
            if (isB && lane == 0) out_states[(size_t)n * H_DIM + c] = hcur;
            continue;
        }
        for (int t = 0; t < T_SEQ; t++, s++) {
            // ---- input-side projection (gi) ----
            float4 xv[4];
            if (!isB) {
                const float4* xp = reinterpret_cast<const float4*>(
                    x + ((size_t)n * T_SEQ + t) * H_DIM + lane * 16);
#pragma unroll
                for (int j = 0; j < 4; j++) xv[j] = xp[j];
            } else {
                wait_flags(g_flag0 + (size_t)s * NCTA_G, lane);   // h0[s] published
                const float* hp = g_h0 + (size_t)s * H_DIM + lane * 16;
#pragma unroll
                for (int j = 0; j < 4; j++) xv[j] = ldrx4(hp + j * 4);
            }
            float gr = 0.f, gz = 0.f, gn = 0.f;
#pragma unroll
            for (int j = 0; j < 4; j++) {
                gr += dot4(wi[0][j], xv[j]);
                gz += dot4(wi[1][j], xv[j]);
                gn += dot4(wi[2][j], xv[j]);
            }
            // ---- recurrent-side projection (gh) ----
            float4 hv[4];
            if (s == 0) {
                hv[0] = hv[1] = hv[2] = hv[3] = make_float4(0.f, 0.f, 0.f, 0.f);
            } else {
                wait_flags(myFlag + (size_t)(s - 1) * NCTA_G, lane);
                const float* hp = myH + (size_t)(s - 1) * H_DIM + lane * 16;
#pragma unroll
                for (int j = 0; j < 4; j++) hv[j] = ldrx4(hp + j * 4);
            }
            float hr = 0.f, hz = 0.f, hn = 0.f;
#pragma unroll
            for (int j = 0; j < 4; j++) {
                hr += dot4(wh[0][j], hv[j]);
                hz += dot4(wh[1][j], hv[j]);
                hn += dot4(wh[2][j], hv[j]);
            }
            // ---- reduce + gates + publish ----
            float ar  = wsum(gr + hr);
            float az  = wsum(gz + hz);
            float ani = wsum(gn);
            float anh = wsum(hn);
            if (lane == 0) {
                float r  = sigmoidf_(ar + b_r);
                float z  = sigmoidf_(az + b_z);
                float nn = tanhf(ani + b_in + r * (anh + b_hn));
                hcur = (1.0f - z) * nn + z * hcur;
                strx1(myH + (size_t)s * H_DIM + c, hcur);   // publish channel (relaxed)
            }
            __syncthreads();                                 // CTA hb: all 8 channels stored
            if (tid == 0) st_rel(&myFlag[(size_t)s * NCTA_G + cta], 1u);  // release flag
        }
        if (isB && lane == 0) out_states[(size_t)n * H_DIM + c] = hcur;
    }
}

extern "C" void kernel_launch(void* const* d_in, const int* in_sizes, int n_in,
                              void* d_out, int out_size) {
    const int*   dates = (const int*)d_in[0];
    const float* x     = (const float*)d_in[1];
    const float* Wih0  = (const float*)d_in[2];
    const float* Whh0  = (const float*)d_in[3];
    const float* bih0  = (const float*)d_in[4];
    const float* bhh0  = (const float*)d_in[5];
    const float* Wih1  = (const float*)d_in[6];
    const float* Whh1  = (const float*)d_in[7];
    const float* bih1  = (const float*)d_in[8];
    const float* bhh1  = (const float*)d_in[9];
    float* out = (float*)d_out;

    // Reference returns (dates, states); if out_size includes the extra N
    // elements, dates (cast to float) come first.
    int with_dates = (out_size >= N_ELEM + N_ELEM * H_DIM) ? 1 : 0;
    float* states = out + (with_dates ? N_ELEM : 0);

    size_t n4 = (size_t)MAXS * NCTA_G / 4;
    init_kernel<<<(int)((n4 + 255) / 256), 256>>>(dates, out, with_dates);
    gru_persistent<<<128, 256>>>(dates, x, Wih0, Whh0, bih0, bhh0,
                                 Wih1, Whh1, bih1, bhh1, states);
}

// round 5
// speedup vs baseline: 2.2549x; 2.2549x over previous
#include <cuda_runtime.h>
#include <cstdint>
#include <math.h>

#define N_ELEM 256
#define T_SEQ  32
#define H_DIM  512
#define MAXS   (N_ELEM * T_SEQ)          // worst-case executed rounds
#define NCTA_G 64                        // CTAs per layer group

// Broadcast buffers for hidden vectors (one slot per executed round, per layer)
__device__ float    g_h0[(size_t)MAXS * H_DIM];
__device__ float    g_h1[(size_t)MAXS * H_DIM];
// Per-CTA publish flags: flag[s][cta] = 1 once CTA cta's 8 channels of round s are visible
__device__ unsigned g_flag0[(size_t)MAXS * NCTA_G];
__device__ unsigned g_flag1[(size_t)MAXS * NCTA_G];
__device__ unsigned g_abort;             // watchdog abort flag

__device__ __forceinline__ float4 ldrx4(const float* p) {
    float4 v;
    asm volatile("ld.relaxed.gpu.global.v4.f32 {%0,%1,%2,%3}, [%4];"
                 : "=f"(v.x), "=f"(v.y), "=f"(v.z), "=f"(v.w)
                 : "l"(p) : "memory");
    return v;
}
__device__ __forceinline__ void strx1(float* p, float v) {
    asm volatile("st.relaxed.gpu.global.f32 [%0], %1;" :: "l"(p), "f"(v) : "memory");
}
__device__ __forceinline__ unsigned ld_acq(const unsigned* p) {
    unsigned v;
    asm volatile("ld.acquire.gpu.global.u32 %0, [%1];" : "=r"(v) : "l"(p) : "memory");
    return v;
}
__device__ __forceinline__ void st_rel(unsigned* p, unsigned v) {
    asm volatile("st.release.gpu.global.u32 [%0], %1;" :: "l"(p), "r"(v) : "memory");
}
// Warp-collective (warp 0 only): wait until all 64 per-CTA flags of a round are
// set. Each lane acquires 2 flags. Backoff via nanosleep keeps L2 queues empty.
__device__ __forceinline__ void wait_flags(const unsigned* f, int lane) {
    unsigned it = 0;
    const unsigned* p = f + lane * 2;
    for (;;) {
        unsigned a = ld_acq(p);
        unsigned b = ld_acq(p + 1);
        if (__all_sync(0xffffffffu, (int)(a & b))) return;
        ++it;
        if (it > 2u) __nanosleep(64);
        if ((it & 255u) == 0u) {
            if (ld_acq(&g_abort) != 0u) return;
            if (it >= (1u << 22)) { st_rel(&g_abort, 1u); return; }
        }
    }
}
__device__ __forceinline__ float wsum(float v) {
    v += __shfl_xor_sync(0xffffffffu, v, 16);
    v += __shfl_xor_sync(0xffffffffu, v, 8);
    v += __shfl_xor_sync(0xffffffffu, v, 4);
    v += __shfl_xor_sync(0xffffffffu, v, 2);
    v += __shfl_xor_sync(0xffffffffu, v, 1);
    return v;
}
__device__ __forceinline__ float dot4(float4 a, float4 b) {
    return a.x * b.x + a.y * b.y + a.z * b.z + a.w * b.w;
}
__device__ __forceinline__ float sigmoidf_(float v) {
    return 1.0f / (1.0f + expf(-v));
}

// Zero flags + abort; optionally write dates (as float) to out.
__global__ void init_kernel(const int* __restrict__ dates, float* __restrict__ out,
                            int write_dates) {
    size_t idx = (size_t)blockIdx.x * blockDim.x + threadIdx.x;
    size_t n4 = (size_t)MAXS * NCTA_G / 4;       // uint4 elements per flag array
    if (idx < n4) {
        reinterpret_cast<uint4*>(g_flag0)[idx] = make_uint4(0u, 0u, 0u, 0u);
        reinterpret_cast<uint4*>(g_flag1)[idx] = make_uint4(0u, 0u, 0u, 0u);
    }
    if (idx == 0) g_abort = 0u;
    if (write_dates && idx < N_ELEM) out[idx] = (float)dates[idx];
}

// Persistent 2-layer pipelined GRU.
// CTAs 0..63   = group A (layer 0): x-projection + recurrence, emits h0[s].
// CTAs 64..127 = group B (layer 1): consumes h0[s], own recurrence, emits h1[s] + states.
__global__ void __launch_bounds__(256, 1)
gru_persistent(const int* __restrict__ dates, const float* __restrict__ x,
               const float* __restrict__ Wih0, const float* __restrict__ Whh0,
               const float* __restrict__ bih0, const float* __restrict__ bhh0,
               const float* __restrict__ Wih1, const float* __restrict__ Whh1,
               const float* __restrict__ bih1, const float* __restrict__ bhh1,
               float* __restrict__ out_states) {
    __shared__ int sdates[N_ELEM];
    int tid = threadIdx.x;
    if (tid < N_ELEM) sdates[tid] = dates[tid];
    __syncthreads();

    int warp = tid >> 5, lane = tid & 31;
    bool isB = (blockIdx.x >= NCTA_G);
    int cta  = isB ? (blockIdx.x - NCTA_G) : blockIdx.x;
    int c    = cta * 8 + warp;                    // owned output channel, 0..511

    const float* Wi = isB ? Wih1 : Wih0;
    const float* Wh = isB ? Whh1 : Whh0;
    const float* bi = isB ? bih1 : bih0;
    const float* bh = isB ? bhh1 : bhh0;

    // Register-resident weights: 3 gate rows (r,z,n) x 16 k-values for both matmuls.
    float4 wi[3][4], wh[3][4];
#pragma unroll
    for (int g = 0; g < 3; g++) {
        const float4* pi = reinterpret_cast<const float4*>(
            Wi + (size_t)(g * H_DIM + c) * H_DIM + lane * 16);
        const float4* ph = reinterpret_cast<const float4*>(
            Wh + (size_t)(g * H_DIM + c) * H_DIM + lane * 16);
#pragma unroll
        for (int j = 0; j < 4; j++) { wi[g][j] = pi[j]; wh[g][j] = ph[j]; }
    }
    float b_r  = bi[c] + bh[c];
    float b_z  = bi[H_DIM + c] + bh[H_DIM + c];
    float b_in = bi[2 * H_DIM + c];
    float b_hn = bh[2 * H_DIM + c];
    float hcur = 0.0f;

    float*    myH    = isB ? g_h1    : g_h0;
    unsigned* myFlag = isB ? g_flag1 : g_flag0;

    int s = 0;                                    // global executed-round index
    for (int n = 0; n < N_ELEM; n++) {
        bool run = (n == 0) || (sdates[n] != sdates[n - 1]);
        if (!run) {
            if (isB && lane == 0) out_states[(size_t)n * H_DIM + c] = hcur;
            continue;
        }
        for (int t = 0; t < T_SEQ; t++, s++) {
            float gr = 0.f, gz = 0.f, gn = 0.f;
            // Group A: x-side projection has no cross-CTA dependency — compute it
            // BEFORE the wait barrier (overlaps with warp 0's polling).
            if (!isB) {
                float4 xv[4];
                const float4* xp = reinterpret_cast<const float4*>(
                    x + ((size_t)n * T_SEQ + t) * H_DIM + lane * 16);
#pragma unroll
                for (int j = 0; j < 4; j++) xv[j] = xp[j];
#pragma unroll
                for (int j = 0; j < 4; j++) {
                    gr += dot4(wi[0][j], xv[j]);
                    gz += dot4(wi[1][j], xv[j]);
                    gn += dot4(wi[2][j], xv[j]);
                }
            }
            // Only warp 0 polls flags; everyone else parks at the barrier.
            if (warp == 0) {
                if (isB)   wait_flags(g_flag0 + (size_t)s * NCTA_G, lane);
                if (s > 0) wait_flags(myFlag + (size_t)(s - 1) * NCTA_G, lane);
            }
            __syncthreads();

            // Group B: input is h0[s] (now published).
            if (isB) {
                float4 xv[4];
                const float* hp = g_h0 + (size_t)s * H_DIM + lane * 16;
#pragma unroll
                for (int j = 0; j < 4; j++) xv[j] = ldrx4(hp + j * 4);
#pragma unroll
                for (int j = 0; j < 4; j++) {
                    gr += dot4(wi[0][j], xv[j]);
                    gz += dot4(wi[1][j], xv[j]);
                    gn += dot4(wi[2][j], xv[j]);
                }
            }
            // Recurrent-side projection.
            float4 hv[4];
            if (s == 0) {
                hv[0] = hv[1] = hv[2] = hv[3] = make_float4(0.f, 0.f, 0.f, 0.f);
            } else {
                const float* hp = myH + (size_t)(s - 1) * H_DIM + lane * 16;
#pragma unroll
                for (int j = 0; j < 4; j++) hv[j] = ldrx4(hp + j * 4);
            }
            float hr = 0.f, hz = 0.f, hn = 0.f;
#pragma unroll
            for (int j = 0; j < 4; j++) {
                hr += dot4(wh[0][j], hv[j]);
                hz += dot4(wh[1][j], hv[j]);
                hn += dot4(wh[2][j], hv[j]);
            }
            // ---- reduce + gates + publish ----
            float ar  = wsum(gr + hr);
            float az  = wsum(gz + hz);
            float ani = wsum(gn);
            float anh = wsum(hn);
            if (lane == 0) {
                float r  = sigmoidf_(ar + b_r);
                float z  = sigmoidf_(az + b_z);
                float nn = tanhf(ani + b_in + r * (anh + b_hn));
                hcur = (1.0f - z) * nn + z * hcur;
                strx1(myH + (size_t)s * H_DIM + c, hcur);   // publish channel (relaxed)
            }
            __syncthreads();                                 // CTA hb: all 8 channels stored
            if (tid == 0) st_rel(&myFlag[(size_t)s * NCTA_G + cta], 1u);  // release flag
        }
        if (isB && lane == 0) out_states[(size_t)n * H_DIM + c] = hcur;
    }
}

extern "C" void kernel_launch(void* const* d_in, const int* in_sizes, int n_in,
                              void* d_out, int out_size) {
    const int*   dates = (const int*)d_in[0];
    const float* x     = (const float*)d_in[1];
    const float* Wih0  = (const float*)d_in[2];
    const float* Whh0  = (const float*)d_in[3];
    const float* bih0  = (const float*)d_in[4];
    const float* bhh0  = (const float*)d_in[5];
    const float* Wih1  = (const float*)d_in[6];
    const float* Whh1  = (const float*)d_in[7];
    const float* bih1  = (const float*)d_in[8];
    const float* bhh1  = (const float*)d_in[9];
    float* out = (float*)d_out;

    // Reference returns (dates, states); if out_size includes the extra N
    // elements, dates (cast to float) come first.
    int with_dates = (out_size >= N_ELEM + N_ELEM * H_DIM) ? 1 : 0;
    float* states = out + (with_dates ? N_ELEM : 0);

    size_t n4 = (size_t)MAXS * NCTA_G / 4;
    init_kernel<<<(int)((n4 + 255) / 256), 256>>>(dates, out, with_dates);
    gru_persistent<<<128, 256>>>(dates, x, Wih0, Whh0, bih0, bhh0,
                                 Wih1, Whh1, bih1, bhh1, states);
}

// round 6
// speedup vs baseline: 2.2768x; 1.0097x over previous
#include <cuda_runtime.h>
#include <cstdint>
#include <math.h>

#define N_ELEM 256
#define T_SEQ  32
#define H_DIM  512
#define MAXS   (N_ELEM * T_SEQ)          // worst-case executed rounds
#define NCTA_G 64                        // CTAs per layer group

// Broadcast buffers for hidden vectors (one slot per executed round, per layer)
__device__ float    g_h0[(size_t)MAXS * H_DIM];
__device__ float    g_h1[(size_t)MAXS * H_DIM];
// Per-CTA publish flags: flag[s][cta] = 1 once CTA cta's 8 channels of round s are visible
__device__ unsigned g_flag0[(size_t)MAXS * NCTA_G];
__device__ unsigned g_flag1[(size_t)MAXS * NCTA_G];
__device__ unsigned g_abort;             // watchdog abort flag

__device__ __forceinline__ float4 ldrx4(const float* p) {
    float4 v;
    asm volatile("ld.relaxed.gpu.global.v4.f32 {%0,%1,%2,%3}, [%4];"
                 : "=f"(v.x), "=f"(v.y), "=f"(v.z), "=f"(v.w)
                 : "l"(p) : "memory");
    return v;
}
__device__ __forceinline__ void strx1(float* p, float v) {
    asm volatile("st.relaxed.gpu.global.f32 [%0], %1;" :: "l"(p), "f"(v) : "memory");
}
__device__ __forceinline__ unsigned ld_acq(const unsigned* p) {
    unsigned v;
    asm volatile("ld.acquire.gpu.global.u32 %0, [%1];" : "=r"(v) : "l"(p) : "memory");
    return v;
}
__device__ __forceinline__ void st_rel(unsigned* p, unsigned v) {
    asm volatile("st.release.gpu.global.u32 [%0], %1;" :: "l"(p), "r"(v) : "memory");
}

// Warp-collective (warp 0 only): tight acquire-poll until all 64 flags in f1
// (and, if f2 != nullptr, all 64 flags in f2) are set. NO nanosleep — HW sleep
// granularity is ~µs and became the round period in R5. 128 polling warps over
// a few cache lines is far below LTS slice limits, so tight polling is safe.
__device__ __forceinline__ void wait_flags2(const unsigned* f1, const unsigned* f2,
                                            int lane) {
    unsigned it = 0;
    const unsigned* p1 = f1 + lane * 2;
    const unsigned* p2 = f2 ? (f2 + lane * 2) : nullptr;
    for (;;) {
        unsigned a = ld_acq(p1) & ld_acq(p1 + 1);
        if (p2) a &= ld_acq(p2) & ld_acq(p2 + 1);
        if (__all_sync(0xffffffffu, (int)a)) return;
        if ((++it & 1023u) == 0u) {
            if (ld_acq(&g_abort) != 0u) return;
            if (it >= (1u << 22)) { st_rel(&g_abort, 1u); return; }
        }
    }
}
__device__ __forceinline__ float wsum(float v) {
    v += __shfl_xor_sync(0xffffffffu, v, 16);
    v += __shfl_xor_sync(0xffffffffu, v, 8);
    v += __shfl_xor_sync(0xffffffffu, v, 4);
    v += __shfl_xor_sync(0xffffffffu, v, 2);
    v += __shfl_xor_sync(0xffffffffu, v, 1);
    return v;
}
__device__ __forceinline__ float dot4(float4 a, float4 b) {
    return a.x * b.x + a.y * b.y + a.z * b.z + a.w * b.w;
}
__device__ __forceinline__ float sigmoidf_(float v) {
    return 1.0f / (1.0f + expf(-v));
}

// Zero flags + abort; optionally write dates (as float) to out.
__global__ void init_kernel(const int* __restrict__ dates, float* __restrict__ out,
                            int write_dates) {
    size_t idx = (size_t)blockIdx.x * blockDim.x + threadIdx.x;
    size_t n4 = (size_t)MAXS * NCTA_G / 4;       // uint4 elements per flag array
    if (idx < n4) {
        reinterpret_cast<uint4*>(g_flag0)[idx] = make_uint4(0u, 0u, 0u, 0u);
        reinterpret_cast<uint4*>(g_flag1)[idx] = make_uint4(0u, 0u, 0u, 0u);
    }
    if (idx == 0) g_abort = 0u;
    if (write_dates && idx < N_ELEM) out[idx] = (float)dates[idx];
}

// Persistent 2-layer pipelined GRU.
// CTAs 0..63   = group A (layer 0): x-projection + recurrence, emits h0[s].
// CTAs 64..127 = group B (layer 1): consumes h0[s], own recurrence, emits h1[s] + states.
__global__ void __launch_bounds__(256, 1)
gru_persistent(const int* __restrict__ dates, const float* __restrict__ x,
               const float* __restrict__ Wih0, const float* __restrict__ Whh0,
               const float* __restrict__ bih0, const float* __restrict__ bhh0,
               const float* __restrict__ Wih1, const float* __restrict__ Whh1,
               const float* __restrict__ bih1, const float* __restrict__ bhh1,
               float* __restrict__ out_states) {
    __shared__ int sdates[N_ELEM];
    int tid = threadIdx.x;
    if (tid < N_ELEM) sdates[tid] = dates[tid];
    __syncthreads();

    int warp = tid >> 5, lane = tid & 31;
    bool isB = (blockIdx.x >= NCTA_G);
    int cta  = isB ? (blockIdx.x - NCTA_G) : blockIdx.x;
    int c    = cta * 8 + warp;                    // owned output channel, 0..511

    const float* Wi = isB ? Wih1 : Wih0;
    const float* Wh = isB ? Whh1 : Whh0;
    const float* bi = isB ? bih1 : bih0;
    const float* bh = isB ? bhh1 : bhh0;

    // Register-resident weights: 3 gate rows (r,z,n) x 16 k-values for both matmuls.
    float4 wi[3][4], wh[3][4];
#pragma unroll
    for (int g = 0; g < 3; g++) {
        const float4* pi = reinterpret_cast<const float4*>(
            Wi + (size_t)(g * H_DIM + c) * H_DIM + lane * 16);
        const float4* ph = reinterpret_cast<const float4*>(
            Wh + (size_t)(g * H_DIM + c) * H_DIM + lane * 16);
#pragma unroll
        for (int j = 0; j < 4; j++) { wi[g][j] = pi[j]; wh[g][j] = ph[j]; }
    }
    float b_r  = bi[c] + bh[c];
    float b_z  = bi[H_DIM + c] + bh[H_DIM + c];
    float b_in = bi[2 * H_DIM + c];
    float b_hn = bh[2 * H_DIM + c];
    float hcur = 0.0f;

    float*    myH    = isB ? g_h1    : g_h0;
    unsigned* myFlag = isB ? g_flag1 : g_flag0;

    int s = 0;                                    // global executed-round index
    for (int n = 0; n < N_ELEM; n++) {
        bool run = (n == 0) || (sdates[n] != sdates[n - 1]);
        if (!run) {
            if (isB && lane == 0) out_states[(size_t)n * H_DIM + c] = hcur;
            continue;
        }
        for (int t = 0; t < T_SEQ; t++, s++) {
            float gr = 0.f, gz = 0.f, gn = 0.f;
            // Group A: x-side projection has no cross-CTA dependency — compute it
            // BEFORE the wait barrier (overlaps with warp 0's polling).
            if (!isB) {
                float4 xv[4];
                const float4* xp = reinterpret_cast<const float4*>(
                    x + ((size_t)n * T_SEQ + t) * H_DIM + lane * 16);
#pragma unroll
                for (int j = 0; j < 4; j++) xv[j] = xp[j];
#pragma unroll
                for (int j = 0; j < 4; j++) {
                    gr += dot4(wi[0][j], xv[j]);
                    gz += dot4(wi[1][j], xv[j]);
                    gn += dot4(wi[2][j], xv[j]);
                }
            }
            // Only warp 0 polls; both dependencies polled in ONE merged loop.
            if (warp == 0) {
                if (isB) {
                    const unsigned* f1 = g_flag0 + (size_t)s * NCTA_G;
                    const unsigned* f2 = (s > 0) ? (g_flag1 + (size_t)(s - 1) * NCTA_G)
                                                 : nullptr;
                    wait_flags2(f1, f2, lane);
                } else if (s > 0) {
                    wait_flags2(g_flag0 + (size_t)(s - 1) * NCTA_G, nullptr, lane);
                }
            }
            __syncthreads();

            // Group B: input is h0[s] (now published).
            if (isB) {
                float4 xv[4];
                const float* hp = g_h0 + (size_t)s * H_DIM + lane * 16;
#pragma unroll
                for (int j = 0; j < 4; j++) xv[j] = ldrx4(hp + j * 4);
#pragma unroll
                for (int j = 0; j < 4; j++) {
                    gr += dot4(wi[0][j], xv[j]);
                    gz += dot4(wi[1][j], xv[j]);
                    gn += dot4(wi[2][j], xv[j]);
                }
            }
            // Recurrent-side projection.
            float4 hv[4];
            if (s == 0) {
                hv[0] = hv[1] = hv[2] = hv[3] = make_float4(0.f, 0.f, 0.f, 0.f);
            } else {
                const float* hp = myH + (size_t)(s - 1) * H_DIM + lane * 16;
#pragma unroll
                for (int j = 0; j < 4; j++) hv[j] = ldrx4(hp + j * 4);
            }
            float hr = 0.f, hz = 0.f, hn = 0.f;
#pragma unroll
            for (int j = 0; j < 4; j++) {
                hr += dot4(wh[0][j], hv[j]);
                hz += dot4(wh[1][j], hv[j]);
                hn += dot4(wh[2][j], hv[j]);
            }
            // ---- reduce + gates + publish ----
            float ar  = wsum(gr + hr);
            float az  = wsum(gz + hz);
            float ani = wsum(gn);
            float anh = wsum(hn);
            if (lane == 0) {
                float r  = sigmoidf_(ar + b_r);
                float z  = sigmoidf_(az + b_z);
                float nn = tanhf(ani + b_in + r * (anh + b_hn));
                hcur = (1.0f - z) * nn + z * hcur;
                strx1(myH + (size_t)s * H_DIM + c, hcur);   // publish channel (relaxed)
            }
            __syncthreads();                                 // CTA hb: all 8 channels stored
            if (tid == 0) st_rel(&myFlag[(size_t)s * NCTA_G + cta], 1u);  // release flag
        }
        if (isB && lane == 0) out_states[(size_t)n * H_DIM + c] = hcur;
    }
}

extern "C" void kernel_launch(void* const* d_in, const int* in_sizes, int n_in,
                              void* d_out, int out_size) {
    const int*   dates = (const int*)d_in[0];
    const float* x     = (const float*)d_in[1];
    const float* Wih0  = (const float*)d_in[2];
    const float* Whh0  = (const float*)d_in[3];
    const float* bih0  = (const float*)d_in[4];
    const float* bhh0  = (const float*)d_in[5];
    const float* Wih1  = (const float*)d_in[6];
    const float* Whh1  = (const float*)d_in[7];
    const float* bih1  = (const float*)d_in[8];
    const float* bhh1  = (const float*)d_in[9];
    float* out = (float*)d_out;

    // Reference returns (dates, states); if out_size includes the extra N
    // elements, dates (cast to float) come first.
    int with_dates = (out_size >= N_ELEM + N_ELEM * H_DIM) ? 1 : 0;
    float* states = out + (with_dates ? N_ELEM : 0);

    size_t n4 = (size_t)MAXS * NCTA_G / 4;
    init_kernel<<<(int)((n4 + 255) / 256), 256>>>(dates, out, with_dates);
    gru_persistent<<<128, 256>>>(dates, x, Wih0, Whh0, bih0, bhh0,
                                 Wih1, Whh1, bih1, bhh1, states);
}